// round 7
// baseline (speedup 1.0000x reference)
#include <cuda_runtime.h>
#include <cuda_bf16.h>
#include <cuda_fp16.h>
#include <cstdint>

typedef long long LL;

// ---------------- problem constants ----------------
#define BB   2
#define SS   1024
#define BS   2048
#define DIM  4096
#define HH   32
#define QL   1536
#define KVL  512
#define NOPE 128
#define ROPE 64
#define VD   128
#define QKH  192
#define CAT  576
#define QD   6144

#define NEGV   (-1e9f)
#define SCALEV 0.07216878364870322f
#define EPSV   1e-6f
#define INV127 (1.f/127.f)

// ---------------- scratch ----------------
__device__ float g_qlora_f[(LL)BS * QL];
__device__ float g_kv_f   [(LL)BS * CAT];
__device__ float g_kvcat_f[(LL)BS * CAT];
__device__ float g_q_f    [(LL)BS * QD];
__device__ float g_qcat_f [(LL)BS * HH * CAT];
__device__ float g_scores [64LL * 1024 * 1024];
__device__ float g_attn_f [(LL)BS * HH * KVL];
__device__ float g_proj_f [(LL)BS * DIM];
// int8 planes (u32 = 4 packed s8 along k), chunk0 / chunk1
__device__ uint32_t g_xq[2][(LL)BS*1024];
__device__ uint32_t g_wqa[2][1536LL*1024];
__device__ uint32_t g_wkva[2][576LL*1024];
__device__ uint32_t g_wqb[2][6144LL*384];
__device__ uint32_t g_wkvb1[2][32LL*512*32];
__device__ uint32_t g_wkvb2[2][32LL*128*128];
__device__ uint32_t g_wo[2][4096LL*1024];
__device__ uint32_t g_qloraq[2][(LL)BS*384];
__device__ uint32_t g_qnope[2][(LL)BS*32*32];
__device__ uint32_t g_qcatq[2][(LL)BS*32*144];
__device__ uint32_t g_kvrow[2][(LL)BS*144];
__device__ uint32_t g_kvT[2][2LL*512*256];
__device__ uint32_t g_Pq[2][64LL*1024*256];
__device__ uint32_t g_attnq[2][(LL)BS*32*128];
__device__ uint32_t g_projq[2][(LL)BS*1024];
// scales (= rowmax/127)
__device__ float s_x[BS], s_wqa[QL], s_wkva[CAT], s_wqb[QD];
__device__ float s_wkvb1[32*512], s_wkvb2[32*128], s_wo[DIM];
__device__ float s_qlora[BS], s_qnope[BS*32], s_qcat[BS*32];
__device__ float s_kvrow[BS], s_kvT[2*512], s_P[64*1024];
__device__ float s_attn[BS*32], s_proj[BS];

// ---------------- helpers ----------------
__device__ __forceinline__ void cp16(uint32_t saddr, const void* g) {
    asm volatile("cp.async.ca.shared.global [%0], [%1], 16;\n" :: "r"(saddr), "l"(g));
}
__device__ __forceinline__ void cp_commit() { asm volatile("cp.async.commit_group;\n"); }
template<int NN> __device__ __forceinline__ void cp_wait() {
    asm volatile("cp.async.wait_group %0;\n" :: "n"(NN));
}
__device__ __forceinline__ void imma(int c[4], const uint32_t a[4], const uint32_t b[2]) {
    asm volatile(
        "mma.sync.aligned.m16n8k32.row.col.s32.s8.s8.s32 "
        "{%0,%1,%2,%3},{%4,%5,%6,%7},{%8,%9},{%0,%1,%2,%3};\n"
        : "+r"(c[0]), "+r"(c[1]), "+r"(c[2]), "+r"(c[3])
        : "r"(a[0]), "r"(a[1]), "r"(a[2]), "r"(a[3]), "r"(b[0]), "r"(b[1]));
}
__device__ __forceinline__ uint32_t pack4(int a, int b, int c, int d) {
    return (uint32_t)(a & 0xFF) | ((uint32_t)(b & 0xFF) << 8)
         | ((uint32_t)(c & 0xFF) << 16) | ((uint32_t)(d & 0xFF) << 24);
}

// ---------------- int8 2-chunk GEMM ----------------
// C[m,n] = sum_k A[m,k]*B[n,k].  A,B as 2 int8 planes [row][k4] u32 + row scales
// (alpha = rowmax/127).  a = (c0 + c1/127)*alpha.
// C = alpha[m]*beta[n]*(acc00 + accX/127), accX = a0*b1 + a1*b0 (int32-exact).
// CTA 128x64, BK=32 (8 u32), 8 warps (4m x 2n), warp tile 32x32.
// OUT: 0 = plain f32, 1 = scores epilogue (scale+causal; masked-tile skip).
// CK: causal K bound (k < m0+128).
template<int OUT, bool CK>
__global__ __launch_bounds__(256, 2)
void gemm_i8(const uint32_t* __restrict__ A0, const uint32_t* __restrict__ A1,
             const uint32_t* __restrict__ B0, const uint32_t* __restrict__ B1,
             const float* __restrict__ sa, const float* __restrict__ sb,
             float* __restrict__ Cf,
             int M, int N, int K4, int lda4, int ldb4, int ldc,
             int sstrA, int sstrB,
             LL bA1, LL bA2, LL bB1, LL bB2,
             LL bSA1, LL bSA2, LL bSB1, LL bSB2,
             LL bC1, LL bC2, int nz2)
{
    const int z = blockIdx.z, z1 = z / nz2, z2 = z - z1 * nz2;
    A0 += z1*bA1 + z2*bA2;  A1 += z1*bA1 + z2*bA2;
    B0 += z1*bB1 + z2*bB2;  B1 += z1*bB1 + z2*bB2;
    sa += z1*bSA1 + z2*bSA2;
    sb += z1*bSB1 + z2*bSB2;
    const LL coff = z1*bC1 + z2*bC2;
    const int m0 = blockIdx.y * 128, n0 = blockIdx.x * 64;
    const int tid = threadIdx.x;

    if (OUT == 1 && n0 >= m0 + 128) {
        for (int e = tid; e < 128 * 64; e += 256) {
            int r = e >> 6, c = e & 63;
            Cf[coff + (LL)(m0 + r) * ldc + n0 + c] = NEGV;
        }
        return;
    }

    __shared__ uint32_t sAm[2][2][1024];   // [stage][chunk][128 rows * 8 u32]
    __shared__ uint32_t sBm[2][2][512];    // [stage][chunk][64 rows * 8 u32]
    const uint32_t sAb = (uint32_t)__cvta_generic_to_shared(&sAm[0][0][0]);
    const uint32_t sBb = (uint32_t)__cvta_generic_to_shared(&sBm[0][0][0]);

    int K4e = K4;
    if (CK) { int kl = (m0 + 128) >> 2; if (kl < K4e) K4e = kl; }
    const int nk = K4e >> 3;

    // fill indexing: A row = tid>>1, half = tid&1 (2 planes per thread).
    //               B: plane = tid>>7, row = (tid&127)>>1, half = tid&1.
    const LL arowA = (LL)(m0 + (tid >> 1)) * lda4 + (tid & 1) * 4;
    const int brw = (tid & 127) >> 1;
    const LL browB = (LL)(n0 + brw) * ldb4 + (tid & 1) * 4;
    const uint32_t* Bsel = (tid >> 7) ? B1 : B0;
    const uint32_t sAd0 = sAb + tid * 16u;
    const uint32_t sBd  = sBb + (uint32_t)(tid >> 7) * 2048u + (uint32_t)(tid & 127) * 16u;

#define FILL(ik, st) { \
        const int kc = (ik) * 8; \
        cp16(sAd0 + (uint32_t)(st) * 8192u,           A0 + arowA + kc); \
        cp16(sAd0 + (uint32_t)(st) * 8192u + 4096u,   A1 + arowA + kc); \
        cp16(sBd  + (uint32_t)(st) * 4096u,           Bsel + browB + kc); \
        cp_commit(); }

    const int lane = tid & 31, wid = tid >> 5;
    const int wm = wid >> 1, wn = wid & 1;
    const int gp = lane >> 2, tg = lane & 3;

    int acc0[2][4][4], accx[2][4][4];
#pragma unroll
    for (int i = 0; i < 2; i++)
#pragma unroll
        for (int j = 0; j < 4; j++)
#pragma unroll
            for (int r = 0; r < 4; r++) { acc0[i][j][r] = 0; accx[i][j][r] = 0; }

    FILL(0, 0);
    for (int ik = 0; ik < nk; ik++) {
        const int cur = ik & 1;
        if (ik + 1 < nk) { FILL(ik + 1, (ik + 1) & 1); cp_wait<1>(); }
        else             { cp_wait<0>(); }
        __syncthreads();

        const uint32_t* As0 = sAm[cur][0];
        const uint32_t* As1 = sAm[cur][1];
        const uint32_t* Bs0 = sBm[cur][0];
        const uint32_t* Bs1 = sBm[cur][1];

        uint32_t b0f[4][2], b1f[4][2];
#pragma unroll
        for (int nf = 0; nf < 4; nf++) {
            int nb = (wn << 5) + (nf << 3) + gp;
            int i0 = nb * 8 + tg;
            b0f[nf][0] = Bs0[i0]; b0f[nf][1] = Bs0[i0 + 4];
            b1f[nf][0] = Bs1[i0]; b1f[nf][1] = Bs1[i0 + 4];
        }
#pragma unroll
        for (int mf = 0; mf < 2; mf++) {
            int mb = (wm << 5) + (mf << 4) + gp;
            int j0 = mb * 8 + tg;
            int j1 = j0 + 64;
            uint32_t a0[4] = { As0[j0], As0[j1], As0[j0 + 4], As0[j1 + 4] };
            uint32_t a1[4] = { As1[j0], As1[j1], As1[j0 + 4], As1[j1 + 4] };
#pragma unroll
            for (int nf = 0; nf < 4; nf++) {
                imma(acc0[mf][nf], a0, b0f[nf]);
                imma(accx[mf][nf], a0, b1f[nf]);
                imma(accx[mf][nf], a1, b0f[nf]);
            }
        }
        __syncthreads();
    }
#undef FILL

    // ---- epilogue
#pragma unroll
    for (int mf = 0; mf < 2; mf++) {
        int m = m0 + (wm << 5) + (mf << 4) + gp;
        float al0 = sa[m * sstrA];
        float al1 = sa[(m + 8) * sstrA];
#pragma unroll
        for (int nf = 0; nf < 4; nf++) {
            int nn = n0 + (wn << 5) + (nf << 3) + 2 * tg;
            float be0 = sb[nn * sstrB];
            float be1 = sb[(nn + 1) * sstrB];
            float v0 = (float)acc0[mf][nf][0] + (float)accx[mf][nf][0] * INV127;
            float v1 = (float)acc0[mf][nf][1] + (float)accx[mf][nf][1] * INV127;
            float v2 = (float)acc0[mf][nf][2] + (float)accx[mf][nf][2] * INV127;
            float v3 = (float)acc0[mf][nf][3] + (float)accx[mf][nf][3] * INV127;
            float2 r0 = make_float2(al0 * be0 * v0, al0 * be1 * v1);
            float2 r1 = make_float2(al1 * be0 * v2, al1 * be1 * v3);
            if (OUT == 1) {
                r0.x = r0.x * SCALEV + ((nn     > m)     ? NEGV : 0.f);
                r0.y = r0.y * SCALEV + ((nn + 1 > m)     ? NEGV : 0.f);
                r1.x = r1.x * SCALEV + ((nn     > m + 8) ? NEGV : 0.f);
                r1.y = r1.y * SCALEV + ((nn + 1 > m + 8) ? NEGV : 0.f);
            }
            *reinterpret_cast<float2*>(Cf + coff + (LL)m * ldc + nn) = r0;
            *reinterpret_cast<float2*>(Cf + coff + (LL)(m + 8) * ldc + nn) = r1;
        }
    }
}

// ---------------- quantrow: per-row 2-chunk int8 quantization ----------------
// row r reads in + (r/RH)*ors + (r%RH)*irs, len elements; outputs planes
// [r][len/4] and alpha[r] = rowmax/127.
__global__ void quantrow(const float* __restrict__ in, uint32_t* __restrict__ q0,
                         uint32_t* __restrict__ q1, float* __restrict__ alpha,
                         int len, int RH, LL irs, LL ors)
{
    const int row = blockIdx.x;
    const float* p = in + (LL)(row / RH) * ors + (LL)(row % RH) * irs;
    const int g4 = len >> 2;
    const int tid = threadIdx.x;
    float4 vv[4];
    int cnt = 0;
    float mx = 0.f;
    for (int g = tid; g < g4; g += 256) {
        float4 v = *reinterpret_cast<const float4*>(p + 4 * g);
        vv[cnt++] = v;
        mx = fmaxf(mx, fmaxf(fmaxf(fabsf(v.x), fabsf(v.y)),
                             fmaxf(fabsf(v.z), fabsf(v.w))));
    }
    __shared__ float red[8];
    __shared__ float sval;
#pragma unroll
    for (int o = 16; o; o >>= 1) mx = fmaxf(mx, __shfl_xor_sync(0xffffffffu, mx, o));
    if ((tid & 31) == 0) red[tid >> 5] = mx;
    __syncthreads();
    if (tid == 0) {
        float t = red[0];
#pragma unroll
        for (int i = 1; i < 8; i++) t = fmaxf(t, red[i]);
        sval = t;
        alpha[row] = t * INV127;
    }
    __syncthreads();
    float s = sval;
    float inv = (s > 0.f) ? 127.f / s : 0.f;
    float sr = s * INV127;
    cnt = 0;
    for (int g = tid; g < g4; g += 256) {
        float4 v = vv[cnt++];
        int cx = __float2int_rn(v.x * inv), cy = __float2int_rn(v.y * inv);
        int cz = __float2int_rn(v.z * inv), cw = __float2int_rn(v.w * inv);
        float rx = fmaf((float)-cx, sr, v.x), ry = fmaf((float)-cy, sr, v.y);
        float rz = fmaf((float)-cz, sr, v.z), rw = fmaf((float)-cw, sr, v.w);
        int dx = __float2int_rn(rx * inv * 127.f), dy = __float2int_rn(ry * inv * 127.f);
        int dz = __float2int_rn(rz * inv * 127.f), dw = __float2int_rn(rw * inv * 127.f);
        q0[(LL)row * g4 + g] = pack4(cx, cy, cz, cw);
        q1[(LL)row * g4 + g] = pack4(dx, dy, dz, dw);
    }
}

// ---------------- colmax: beta[c] = max_r |in[r,c]| / 127 ----------------
__global__ void colmax(const float* __restrict__ in, float* __restrict__ beta,
                       int R, int C, LL irs, LL ibs, LL obs)
{
    int c = blockIdx.x * 256 + threadIdx.x;
    int z = blockIdx.y;
    if (c >= C) return;
    const float* p = in + (LL)z * ibs + c;
    float m = 0.f;
#pragma unroll 4
    for (int r = 0; r < R; r++) m = fmaxf(m, fabsf(p[(LL)r * irs]));
    beta[(LL)z * obs + c] = m * INV127;
}

// ---------------- tquant: transpose + 2-chunk quantize ----------------
// in [R][C] -> planes rows c (K=R): q[z][c][R/4]; beta precomputed by colmax.
__global__ void tquant(const float* __restrict__ in, const float* __restrict__ beta,
                       uint32_t* __restrict__ q0, uint32_t* __restrict__ q1,
                       int R, int C, LL irs, LL ibs, LL bOff, LL obs)
{
    __shared__ float s[64][33];
    const int z = blockIdx.z;
    const int r0 = blockIdx.y * 64, c0 = blockIdx.x * 32;
    const float* base = in + (LL)z * ibs;
    const int t = threadIdx.x;
#pragma unroll
    for (int i = 0; i < 8; i++) {
        int idx = t + 256 * i;
        int lr = idx >> 5, lc = idx & 31;
        s[lr][lc] = base[(LL)(r0 + lr) * irs + c0 + lc];
    }
    __syncthreads();
    const int oc = t >> 3, og = t & 7;
    const int c = c0 + oc;
    float b = beta[(LL)z * bOff + c];
    float inv = (b > 0.f) ? 1.f / b : 0.f;
    float sr = b;
    const int R4 = R >> 2;
#pragma unroll
    for (int half = 0; half < 2; half++) {
        int r4 = og + 8 * half;      // 0..15
        int cc[4], dd[4];
#pragma unroll
        for (int j = 0; j < 4; j++) {
            float v = s[4 * r4 + j][oc];
            int c0i = __float2int_rn(v * inv);
            float r = fmaf((float)-c0i, sr, v);
            int c1i = __float2int_rn(r * inv * 127.f);
            cc[j] = c0i; dd[j] = c1i;
        }
        LL o = (LL)z * obs + (LL)c * R4 + (r0 >> 2) + r4;
        q0[o] = pack4(cc[0], cc[1], cc[2], cc[3]);
        q1[o] = pack4(dd[0], dd[1], dd[2], dd[3]);
    }
}

// ---------------- rmsnorm (in place) ----------------
__global__ void rmsnorm_k(float* __restrict__ x, const float* __restrict__ w, int len)
{
    float* row = x + (LL)blockIdx.x * len;
    const int tid = threadIdx.x;
    float ss = 0.f;
    for (int i = tid; i < len; i += 256) { float v = row[i]; ss += v * v; }
    __shared__ float red[8];
    __shared__ float sc_s;
#pragma unroll
    for (int o = 16; o; o >>= 1) ss += __shfl_xor_sync(0xffffffffu, ss, o);
    if ((tid & 31) == 0) red[tid >> 5] = ss;
    __syncthreads();
    if (tid == 0) {
        float t = 0.f;
#pragma unroll
        for (int i = 0; i < 8; i++) t += red[i];
        sc_s = rsqrtf(t / (float)len + EPSV);
    }
    __syncthreads();
    float sc = sc_s;
    for (int i = tid; i < len; i += 256) row[i] = row[i] * sc * w[i];
}

// ---- kvpost: rmsnorm(c_kv)*w -> kvcat[0:512]; rope(k_pe) -> kvcat[512:576]
__global__ void kvpost_k(const float* __restrict__ kv, const float* __restrict__ w,
                         const float* __restrict__ fc, float* __restrict__ o)
{
    const int bs = blockIdx.x;
    const float* row = kv + (LL)bs * CAT;
    float* out = o + (LL)bs * CAT;
    const int tid = threadIdx.x;
    float2 v = *reinterpret_cast<const float2*>(row + 2 * tid);
    float ss = v.x * v.x + v.y * v.y;
    __shared__ float red[8];
    __shared__ float sc_s;
#pragma unroll
    for (int oo = 16; oo; oo >>= 1) ss += __shfl_xor_sync(0xffffffffu, ss, oo);
    if ((tid & 31) == 0) red[tid >> 5] = ss;
    __syncthreads();
    if (tid == 0) {
        float t = 0.f;
#pragma unroll
        for (int i = 0; i < 8; i++) t += red[i];
        sc_s = rsqrtf(t / (float)KVL + EPSV);
    }
    __syncthreads();
    float sc = sc_s;
    *reinterpret_cast<float2*>(out + 2 * tid) =
        make_float2(v.x * sc * w[2 * tid], v.y * sc * w[2 * tid + 1]);
    if (tid < 32) {
        int s = bs & (SS - 1);
        float e  = row[KVL + 2 * tid];
        float od = row[KVL + 2 * tid + 1];
        float c  = fc[s * ROPE + 2 * tid];
        float sn = fc[s * ROPE + 2 * tid + 1];
        out[KVL + 2 * tid]     = e * c - od * sn;
        out[KVL + 2 * tid + 1] = e * sn + od * c;
    }
}

// ---- rope(q_pe): q_f -> qcat_f[...,512:576] ----
__global__ void ropeq_k(const float* __restrict__ q, const float* __restrict__ fc,
                        float* __restrict__ qcat)
{
    const int bs = blockIdx.x;
    const int s = bs & (SS - 1);
    for (int t = threadIdx.x; t < HH * 32; t += 256) {
        int h = t >> 5, i = t & 31;
        const float* src = q + (LL)bs * QD + h * QKH + NOPE + 2 * i;
        float e = src[0], o = src[1];
        float c  = fc[s * ROPE + 2 * i];
        float sn = fc[s * ROPE + 2 * i + 1];
        float* dst = qcat + (LL)bs * (HH * CAT) + h * CAT + KVL + 2 * i;
        dst[0] = e * c - o * sn;
        dst[1] = e * sn + o * c;
    }
}

// ---- softmax + fused P quantization ----
// max(P) = 1/Z exactly (the max logit maps to exp(0)=1), so alpha = inv/127,
// c0 = rn(127*v), c1 = rn(16129*v - 127*c0) where v = exp(x-mx) in [0,1].
__global__ void softmax_k(const float* __restrict__ S,
                          uint32_t* __restrict__ p0, uint32_t* __restrict__ p1,
                          float* __restrict__ alpha)
{
    const LL row = blockIdx.x;
    const float* r = S + row * 1024;
    const int tid = threadIdx.x;
    float4 v = *reinterpret_cast<const float4*>(r + 4 * tid);
    float mx = fmaxf(fmaxf(v.x, v.y), fmaxf(v.z, v.w));
    __shared__ float red[8];
    __shared__ float bval;
#pragma unroll
    for (int o = 16; o; o >>= 1) mx = fmaxf(mx, __shfl_xor_sync(0xffffffffu, mx, o));
    if ((tid & 31) == 0) red[tid >> 5] = mx;
    __syncthreads();
    if (tid == 0) {
        float t = red[0];
#pragma unroll
        for (int i = 1; i < 8; i++) t = fmaxf(t, red[i]);
        bval = t;
    }
    __syncthreads();
    mx = bval;
    v.x = __expf(v.x - mx); v.y = __expf(v.y - mx);
    v.z = __expf(v.z - mx); v.w = __expf(v.w - mx);
    float sum = v.x + v.y + v.z + v.w;
    __syncthreads();
#pragma unroll
    for (int o = 16; o; o >>= 1) sum += __shfl_xor_sync(0xffffffffu, sum, o);
    if ((tid & 31) == 0) red[tid >> 5] = sum;
    __syncthreads();
    if (tid == 0) {
        float t = 0.f;
#pragma unroll
        for (int i = 0; i < 8; i++) t += red[i];
        float inv = 1.f / t;
        bval = inv;
        alpha[row] = inv * INV127;
    }
    __syncthreads();
    (void)bval;
    int cx = __float2int_rn(v.x * 127.f), cy = __float2int_rn(v.y * 127.f);
    int cz = __float2int_rn(v.z * 127.f), cw = __float2int_rn(v.w * 127.f);
    int dx = __float2int_rn(fmaf(16129.f, v.x, (float)(-127 * cx)));
    int dy = __float2int_rn(fmaf(16129.f, v.y, (float)(-127 * cy)));
    int dz = __float2int_rn(fmaf(16129.f, v.z, (float)(-127 * cz)));
    int dw = __float2int_rn(fmaf(16129.f, v.w, (float)(-127 * cw)));
    p0[row * 256 + tid] = pack4(cx, cy, cz, cw);
    p1[row * 256 + tid] = pack4(dx, dy, dz, dw);
}

// ---------------- host ----------------
extern "C" void kernel_launch(void* const* d_in, const int* in_sizes, int n_in,
                              void* d_out, int out_size)
{
    (void)in_sizes; (void)n_in; (void)out_size;
    const float* x      = (const float*)d_in[0];
    const float* fc     = (const float*)d_in[1];
    const float* wq_a   = (const float*)d_in[3];
    const float* qnw    = (const float*)d_in[4];
    const float* wq_b   = (const float*)d_in[5];
    const float* wkv_a  = (const float*)d_in[6];
    const float* kvnw   = (const float*)d_in[7];
    const float* wkv_b  = (const float*)d_in[8];
    const float* wo     = (const float*)d_in[9];
    float* out = (float*)d_out;

#define GS(p, s) cudaGetSymbolAddress((void**)&p, s)
    float *qlora_f, *kv_f, *kvcat_f, *q_f, *qcat_f, *scores, *attn_f, *proj_f;
    GS(qlora_f, g_qlora_f); GS(kv_f, g_kv_f); GS(kvcat_f, g_kvcat_f);
    GS(q_f, g_q_f); GS(qcat_f, g_qcat_f); GS(scores, g_scores);
    GS(attn_f, g_attn_f); GS(proj_f, g_proj_f);
    uint32_t *xq, *wqa, *wkva, *wqb, *wkvb1, *wkvb2, *woq;
    uint32_t *qloraq, *qnopeq, *qcatq, *kvrow, *kvT, *Pq, *attnq, *projq;
    GS(xq, g_xq); GS(wqa, g_wqa); GS(wkva, g_wkva); GS(wqb, g_wqb);
    GS(wkvb1, g_wkvb1); GS(wkvb2, g_wkvb2); GS(woq, g_wo);
    GS(qloraq, g_qloraq); GS(qnopeq, g_qnope); GS(qcatq, g_qcatq);
    GS(kvrow, g_kvrow); GS(kvT, g_kvT); GS(Pq, g_Pq);
    GS(attnq, g_attnq); GS(projq, g_projq);
    float *sx, *swqa, *swkva, *swqb, *swkvb1, *swkvb2, *swo;
    float *sqlora, *sqnope, *sqcat, *skvrow, *skvT, *sP, *sattn, *sproj;
    GS(sx, s_x); GS(swqa, s_wqa); GS(swkva, s_wkva); GS(swqb, s_wqb);
    GS(swkvb1, s_wkvb1); GS(swkvb2, s_wkvb2); GS(swo, s_wo);
    GS(sqlora, s_qlora); GS(sqnope, s_qnope); GS(sqcat, s_qcat);
    GS(skvrow, s_kvrow); GS(skvT, s_kvT); GS(sP, s_P);
    GS(sattn, s_attn); GS(sproj, s_proj);
#undef GS
    // plane1 offsets (second chunk)
#define P2(base, sz) (base), (base) + (LL)(sz)
    const LL SZ_X = (LL)BS*1024, SZ_WQA = 1536LL*1024, SZ_WKVA = 576LL*1024;
    const LL SZ_WQB = 6144LL*384, SZ_WKVB1 = 32LL*512*32, SZ_WKVB2 = 32LL*128*128;
    const LL SZ_WO = 4096LL*1024, SZ_QLORA = (LL)BS*384, SZ_QNOPE = (LL)BS*32*32;
    const LL SZ_QCAT = (LL)BS*32*144, SZ_KVR = (LL)BS*144, SZ_KVT = 2LL*512*256;
    const LL SZ_P = 64LL*1024*256, SZ_ATTN = (LL)BS*32*128, SZ_PROJ = (LL)BS*1024;

    // ---- quant pre-passes (launch order puts gemm1 at capture slot 6)
    quantrow<<<BS, 256>>>(x, P2(xq, SZ_X), sx, 4096, 1, 0, 4096);                 // 1
    colmax<<<dim3(6, 1), 256>>>(wq_a, swqa, DIM, QL, QL, 0, 0);                   // 2
    tquant<<<dim3(48, 64, 1), 256>>>(wq_a, swqa, P2(wqa, SZ_WQA), DIM, QL, QL, 0, 0, 0); // 3
    colmax<<<dim3(3, 1), 256>>>(wkv_a, swkva, DIM, CAT, CAT, 0, 0);               // 4
    tquant<<<dim3(18, 64, 1), 256>>>(wkv_a, swkva, P2(wkva, SZ_WKVA), DIM, CAT, CAT, 0, 0, 0); // 5
    // 6: big GEMM — profiled launch
    gemm_i8<0,false><<<dim3(24,16,1), 256>>>(P2(xq, SZ_X), P2(wqa, SZ_WQA),
        sx, swqa, qlora_f, BS, QL, 1024, 1024, 1024, QL, 1, 1,
        0,0, 0,0, 0,0, 0,0, 0,0, 1);
    gemm_i8<0,false><<<dim3(9,16,1), 256>>>(P2(xq, SZ_X), P2(wkva, SZ_WKVA),
        sx, swkva, kv_f, BS, CAT, 1024, 1024, 1024, CAT, 1, 1,
        0,0, 0,0, 0,0, 0,0, 0,0, 1);
    rmsnorm_k<<<BS, 256>>>(qlora_f, qnw, QL);
    quantrow<<<BS, 256>>>(qlora_f, P2(qloraq, SZ_QLORA), sqlora, QL, 1, 0, QL);
    colmax<<<dim3(24, 1), 256>>>(wq_b, swqb, QL, QD, QD, 0, 0);
    tquant<<<dim3(192, 24, 1), 256>>>(wq_b, swqb, P2(wqb, SZ_WQB), QL, QD, QD, 0, 0, 0);
    gemm_i8<0,false><<<dim3(96,16,1), 256>>>(P2(qloraq, SZ_QLORA), P2(wqb, SZ_WQB),
        sqlora, swqb, q_f, BS, QD, 384, 384, 384, QD, 1, 1,
        0,0, 0,0, 0,0, 0,0, 0,0, 1);
    kvpost_k<<<BS, 256>>>(kv_f, kvnw, fc, kvcat_f);
    quantrow<<<BS, 256>>>(kvcat_f, P2(kvrow, SZ_KVR), skvrow, CAT, 1, 0, CAT);
    colmax<<<dim3(2, 2), 256>>>(kvcat_f, skvT, SS, KVL, CAT, (LL)SS*CAT, KVL);
    tquant<<<dim3(16, 16, 2), 256>>>(kvcat_f, skvT, P2(kvT, SZ_KVT),
        SS, KVL, CAT, (LL)SS*CAT, KVL, (LL)KVL*256);
    quantrow<<<BS*32, 256>>>(q_f, P2(qnopeq, SZ_QNOPE), sqnope, NOPE, 32, QKH, QD);
    ropeq_k<<<BS, 256>>>(q_f, fc, qcat_f);
    colmax<<<dim3(2, 32), 256>>>(wkv_b, swkvb1, NOPE, KVL, KVL, (LL)256*KVL, KVL);
    tquant<<<dim3(16, 2, 32), 256>>>(wkv_b, swkvb1, P2(wkvb1, SZ_WKVB1),
        NOPE, KVL, KVL, (LL)256*KVL, KVL, (LL)KVL*32);
    // qcat nope = q_nope @ wkv_b1^T (per head)
    gemm_i8<0,false><<<dim3(8,16,HH), 256>>>(P2(qnopeq, SZ_QNOPE), P2(wkvb1, SZ_WKVB1),
        sqnope, swkvb1, qcat_f, BS, KVL, 32, 1024, 32, HH*CAT, 32, 1,
        0, 32, 0, (LL)KVL*32, 0, 1, 0, KVL, 0, CAT, HH);
    quantrow<<<BS*32, 256>>>(qcat_f, P2(qcatq, SZ_QCAT), sqcat, CAT, 1, 0, CAT);
    // scores
    gemm_i8<1,false><<<dim3(16,8,BB*HH), 256>>>(P2(qcatq, SZ_QCAT), P2(kvrow, SZ_KVR),
        sqcat, skvrow, scores, SS, SS, 144, 32*144, 144, SS, 32, 1,
        (LL)1024*32*144, 144, (LL)1024*144, 0,
        (LL)32*1024, 1, 1024, 0,
        (LL)32*1024*1024, (LL)1024*1024, HH);
    softmax_k<<<64*1024, 256>>>(scores, P2(Pq, SZ_P), sP);
    // attn = P @ kv^T (causal K bound)
    gemm_i8<0,true><<<dim3(8,8,BB*HH), 256>>>(P2(Pq, SZ_P), P2(kvT, SZ_KVT),
        sP, skvT, attn_f, SS, KVL, 256, 256, 256, HH*KVL, 1, 1,
        (LL)32*1024*256, (LL)1024*256, (LL)KVL*256, 0,
        (LL)32*1024, 1024, 512, 0,
        (LL)1024*HH*KVL, KVL, HH);
    quantrow<<<BS*32, 256>>>(attn_f, P2(attnq, SZ_ATTN), sattn, KVL, 1, 0, KVL);
    quantrow<<<32*128, 256>>>(wkv_b + (LL)NOPE*KVL, P2(wkvb2, SZ_WKVB2), swkvb2,
                              KVL, 128, KVL, (LL)256*KVL);
    // proj = attn @ wkv_b2 (per head)
    gemm_i8<0,false><<<dim3(2,16,HH), 256>>>(P2(attnq, SZ_ATTN), P2(wkvb2, SZ_WKVB2),
        sattn, swkvb2, proj_f, BS, VD, 128, 32*128, 128, DIM, 32, 1,
        0, 128, 0, (LL)128*128, 0, 1, 0, 128, 0, VD, HH);
    quantrow<<<BS, 256>>>(proj_f, P2(projq, SZ_PROJ), sproj, DIM, 1, 0, DIM);
    colmax<<<dim3(16, 1), 256>>>(wo, swo, DIM, DIM, DIM, 0, 0);
    tquant<<<dim3(128, 64, 1), 256>>>(wo, swo, P2(woq, SZ_WO), DIM, DIM, DIM, 0, 0, 0);
    // out = proj @ wo
    gemm_i8<0,false><<<dim3(64,16,1), 256>>>(P2(projq, SZ_PROJ), P2(woq, SZ_WO),
        sproj, swo, out, BS, DIM, 1024, 1024, 1024, DIM, 1, 1,
        0,0, 0,0, 0,0, 0,0, 0,0, 1);
#undef P2
}

// round 8
// speedup vs baseline: 2.9394x; 2.9394x over previous
#include <cuda_runtime.h>
#include <cuda_bf16.h>
#include <cuda_fp16.h>
#include <cstdint>

typedef long long LL;

// ---------------- problem constants ----------------
#define BB   2
#define SS   1024
#define BS   2048          // B*S
#define DIM  4096
#define HH   32
#define QL   1536
#define KVL  512
#define NOPE 128
#define ROPE 64
#define VD   128
#define QKH  192           // NOPE+ROPE
#define CAT  576           // KVL+ROPE
#define QD   6144          // H*QKH

#define NEGV   (-1e9f)
#define SCALEV 0.07216878364870322f   // 192^-0.5
#define EPSV   1e-6f

// ---------------- scratch (device globals) ----------
__device__ float g_qlora[(LL)BS * QL];
__device__ float g_kv   [(LL)BS * CAT];
__device__ float g_kvcat[(LL)BS * CAT];          // [norm(c_kv) | rope(k_pe)]
__device__ float g_q    [(LL)BS * QD];           // rope applied in place on pe part
__device__ float g_Kcat [64LL * SS * QKH];       // (b,h,t,192) = [K_head | k_pe]
__device__ float g_Vt   [64LL * VD * SS];        // (b,h,d,t)   = V_head^T
__device__ float g_scores[64LL * SS * SS];       // (b,h,s,t)
__device__ float g_proj [(LL)BS * DIM];          // (bs, h*VD+d)

// ---------------- split-FP16 3-pass tensor-core tiled GEMM (R4-proven) ------
// C[m,n] = sum_k A[m,k] * B(k,n) ; TB: B stored [N,K] row-major (A @ B^T)
// EPI==1: scores epilogue (v*SCALE + causal NEG) with fully-masked tile skip
// CK: causal K-bound (k limited to m0+128)
// CTA tile 128x128, BK=16, 8 warps (2m x 4n), warp tile 64x32.
// Precision: x = hi(fp16)+lo(fp16); D += ah*bh + ah*bl + al*bh  (~2^-24 dropped)
static const int BM = 128, BN = 128, BK = 16;
#define PK 12      // u32 pitch for [row][k2] tiles

__device__ __forceinline__ void split2(float x, float y, uint32_t& hi, uint32_t& lo) {
    __half hx = __float2half_rn(x), hy = __float2half_rn(y);
    float rx = x - __half2float(hx);
    float ry = y - __half2float(hy);
    __half2 h = __halves2half2(hx, hy);
    __half2 l = __floats2half2_rn(rx, ry);
    hi = *reinterpret_cast<uint32_t*>(&h);
    lo = *reinterpret_cast<uint32_t*>(&l);
}
__device__ __forceinline__ void mma16(float c[4], const uint32_t a[4], const uint32_t b[2]) {
    asm volatile(
        "mma.sync.aligned.m16n8k16.row.col.f32.f16.f16.f32 "
        "{%0,%1,%2,%3},{%4,%5,%6,%7},{%8,%9},{%0,%1,%2,%3};\n"
        : "+f"(c[0]), "+f"(c[1]), "+f"(c[2]), "+f"(c[3])
        : "r"(a[0]), "r"(a[1]), "r"(a[2]), "r"(a[3]), "r"(b[0]), "r"(b[1]));
}

template<bool TB, int EPI, bool CK>
__global__ __launch_bounds__(256, 2)
void gemm_k(const float* __restrict__ A, const float* __restrict__ Bp,
            float* __restrict__ C,
            int M, int N, int K,
            int lda, int ldb, int ldc,
            LL bA1, LL bA2, LL bB1, LL bB2, LL bC1, LL bC2, int nz2)
{
    const int z  = blockIdx.z;
    const int z1 = z / nz2;
    const int z2 = z - z1 * nz2;
    A  += z1 * bA1 + z2 * bA2;
    Bp += z1 * bB1 + z2 * bB2;
    C  += z1 * bC1 + z2 * bC2;

    const int m0  = blockIdx.y * BM;
    const int n0  = blockIdx.x * BN;
    const int tid = threadIdx.x;

    if (EPI == 1 && n0 >= m0 + BM) {
        for (int e = tid; e < BM * BN; e += 256) {
            int r = e >> 7, c = e & 127;
            if (n0 + c < N) C[(LL)(m0 + r) * ldc + n0 + c] = NEGV;
        }
        return;
    }

    __shared__ uint32_t Ah[BM * PK], Al[BM * PK];
    __shared__ uint32_t Bh[BN * PK], Bl[BN * PK];

    const int lane = tid & 31, warp = tid >> 5;
    const int wm = warp >> 2, wn = warp & 3;
    const int gp = lane >> 2, tg = lane & 3;

    float acc[4][4][4];
#pragma unroll
    for (int i = 0; i < 4; i++)
#pragma unroll
        for (int j = 0; j < 4; j++)
#pragma unroll
            for (int r = 0; r < 4; r++) acc[i][j][r] = 0.f;

    int Keff = K;
    if (CK) { int km = m0 + BM; Keff = (km < K) ? km : K; }

    const int am = tid >> 2;          // 0..63 rows (A / TB-B loads)
    const int ak = (tid & 3) << 2;    // k offset 0,4,8,12
    const int k2a = (tid & 3) << 1;   // k2 offset 0,2,4,6
    const int bnn  = tid & 127;
    const int bkh  = (tid >> 7) << 2;

    for (int k0 = 0; k0 < Keff; k0 += BK) {
        // ---- A tile -> [m][k2] (hi/lo)
#pragma unroll
        for (int p = 0; p < 2; p++) {
            int m = am + (p << 6);
            float4 v = *reinterpret_cast<const float4*>(
                A + (LL)(m0 + m) * lda + k0 + ak);
            uint32_t h0, l0, h1, l1;
            split2(v.x, v.y, h0, l0);
            split2(v.z, v.w, h1, l1);
            Ah[m * PK + k2a]     = h0;  Ah[m * PK + k2a + 1] = h1;
            Al[m * PK + k2a]     = l0;  Al[m * PK + k2a + 1] = l1;
        }
        // ---- B tile -> [n][k2] (hi/lo)
        if (!TB) {   // gmem [k][n]: transpose in flight
#pragma unroll
            for (int q = 0; q < 4; q++) {
                int kk = bkh + q;
                float f0 = 0.f, f1 = 0.f;
                if (n0 + bnn < N) {
                    f0 = Bp[(LL)(k0 + 2 * kk)     * ldb + n0 + bnn];
                    f1 = Bp[(LL)(k0 + 2 * kk + 1) * ldb + n0 + bnn];
                }
                uint32_t h, l;
                split2(f0, f1, h, l);
                Bh[bnn * PK + kk] = h;
                Bl[bnn * PK + kk] = l;
            }
        } else {     // gmem [n][k]
#pragma unroll
            for (int p = 0; p < 2; p++) {
                int n = am + (p << 6);
                float4 v = make_float4(0.f, 0.f, 0.f, 0.f);
                if (n0 + n < N)
                    v = *reinterpret_cast<const float4*>(
                        Bp + (LL)(n0 + n) * ldb + k0 + ak);
                uint32_t h0, l0, h1, l1;
                split2(v.x, v.y, h0, l0);
                split2(v.z, v.w, h1, l1);
                Bh[n * PK + k2a]     = h0;  Bh[n * PK + k2a + 1] = h1;
                Bl[n * PK + k2a]     = l0;  Bl[n * PK + k2a + 1] = l1;
            }
        }
        __syncthreads();

        uint32_t bhf[4][2], blf[4][2];
#pragma unroll
        for (int nf = 0; nf < 4; nf++) {
            int nb = (wn << 5) + (nf << 3) + gp;
            bhf[nf][0] = Bh[nb * PK + tg];
            bhf[nf][1] = Bh[nb * PK + tg + 4];
            blf[nf][0] = Bl[nb * PK + tg];
            blf[nf][1] = Bl[nb * PK + tg + 4];
        }
#pragma unroll
        for (int mf = 0; mf < 4; mf++) {
            int mb = (wm << 6) + (mf << 4) + gp;
            int j0 = mb * PK + tg;
            int j1 = (mb + 8) * PK + tg;
            uint32_t ahf[4] = { Ah[j0], Ah[j1], Ah[j0 + 4], Ah[j1 + 4] };
            uint32_t alf[4] = { Al[j0], Al[j1], Al[j0 + 4], Al[j1 + 4] };
#pragma unroll
            for (int nf = 0; nf < 4; nf++) {
                mma16(acc[mf][nf], ahf, bhf[nf]);
                mma16(acc[mf][nf], ahf, blf[nf]);
                mma16(acc[mf][nf], alf, bhf[nf]);
            }
        }
        __syncthreads();
    }

    // ---- store
#pragma unroll
    for (int mf = 0; mf < 4; mf++) {
#pragma unroll
        for (int nf = 0; nf < 4; nf++) {
            int n = n0 + (wn << 5) + (nf << 3) + 2 * tg;
#pragma unroll
            for (int h = 0; h < 2; h++) {
                int m = m0 + (wm << 6) + (mf << 4) + gp + h * 8;
                float2 v = make_float2(acc[mf][nf][2 * h], acc[mf][nf][2 * h + 1]);
                if (EPI == 1) {
                    v.x = v.x * SCALEV + ((n + 0 > m) ? NEGV : 0.f);
                    v.y = v.y * SCALEV + ((n + 1 > m) ? NEGV : 0.f);
                }
                LL ro = (LL)m * ldc;
                if (n + 1 < N) {
                    *reinterpret_cast<float2*>(C + ro + n) = v;
                } else {
                    if (n < N) C[ro + n] = v.x;
                    if (n + 1 < N) C[ro + n + 1] = v.y;
                }
            }
        }
    }
}

// ---------------- rmsnorm (in place) ----------------
__global__ void rmsnorm_k(float* __restrict__ x, const float* __restrict__ w, int len)
{
    float* row = x + (LL)blockIdx.x * len;
    const int tid = threadIdx.x;
    float ss = 0.f;
    for (int i = tid; i < len; i += 256) { float v = row[i]; ss += v * v; }
    __shared__ float red[8];
    __shared__ float sc_s;
#pragma unroll
    for (int o = 16; o; o >>= 1) ss += __shfl_xor_sync(0xffffffffu, ss, o);
    if ((tid & 31) == 0) red[tid >> 5] = ss;
    __syncthreads();
    if (tid == 0) {
        float t = 0.f;
#pragma unroll
        for (int i = 0; i < 8; i++) t += red[i];
        sc_s = rsqrtf(t / (float)len + EPSV);
    }
    __syncthreads();
    float sc = sc_s;
    for (int i = tid; i < len; i += 256) row[i] = row[i] * sc * w[i];
}

// ---- kvpost: rmsnorm(c_kv)*w -> kvcat[0:512]; rope(k_pe) -> kvcat[512:576]
//      AND broadcast roped k_pe into Kcat[b][h][t][128:192] for all 32 heads.
__global__ void kvpost_k(const float* __restrict__ kv, const float* __restrict__ w,
                         const float* __restrict__ fc, float* __restrict__ o,
                         float* __restrict__ Kcat)
{
    const int bs = blockIdx.x;
    const float* row = kv + (LL)bs * CAT;
    float* out = o + (LL)bs * CAT;
    const int tid = threadIdx.x;
    float2 v = *reinterpret_cast<const float2*>(row + 2 * tid);
    float ss = v.x * v.x + v.y * v.y;
    __shared__ float red[8];
    __shared__ float sc_s;
#pragma unroll
    for (int oo = 16; oo; oo >>= 1) ss += __shfl_xor_sync(0xffffffffu, ss, oo);
    if ((tid & 31) == 0) red[tid >> 5] = ss;
    __syncthreads();
    if (tid == 0) {
        float t = 0.f;
#pragma unroll
        for (int i = 0; i < 8; i++) t += red[i];
        sc_s = rsqrtf(t / (float)KVL + EPSV);
    }
    __syncthreads();
    float sc = sc_s;
    *reinterpret_cast<float2*>(out + 2 * tid) =
        make_float2(v.x * sc * w[2 * tid], v.y * sc * w[2 * tid + 1]);
    if (tid < 32) {
        int t = bs & (SS - 1);
        int b = bs >> 10;
        float e  = row[KVL + 2 * tid];
        float od = row[KVL + 2 * tid + 1];
        float c  = fc[t * ROPE + 2 * tid];
        float sn = fc[t * ROPE + 2 * tid + 1];
        float re = e * c - od * sn;
        float ro = e * sn + od * c;
        out[KVL + 2 * tid]     = re;
        out[KVL + 2 * tid + 1] = ro;
        float2 pr = make_float2(re, ro);
#pragma unroll
        for (int h = 0; h < HH; h++) {
            LL base = (((LL)(b * HH + h)) * SS + t) * QKH + NOPE + 2 * tid;
            *reinterpret_cast<float2*>(Kcat + base) = pr;
        }
    }
}

// ---- rope(q_pe) IN PLACE on q[..., h*192+128 : h*192+192] ----
__global__ void ropeq_k(float* __restrict__ q, const float* __restrict__ fc)
{
    const int bs = blockIdx.x;
    const int s = bs & (SS - 1);
    for (int t = threadIdx.x; t < HH * 32; t += 256) {
        int h = t >> 5, i = t & 31;
        float* p = q + (LL)bs * QD + h * QKH + NOPE + 2 * i;
        float e = p[0], o = p[1];
        float c  = fc[s * ROPE + 2 * i];
        float sn = fc[s * ROPE + 2 * i + 1];
        p[0] = e * c - o * sn;
        p[1] = e * sn + o * c;
    }
}

// ---- softmax over rows of 1024 (in place, fp32) ----
__global__ void softmax_k(float* __restrict__ S)
{
    float* row = S + (LL)blockIdx.x * 1024;
    const int tid = threadIdx.x;
    float4 v = *reinterpret_cast<const float4*>(row + 4 * tid);
    float mx = fmaxf(fmaxf(v.x, v.y), fmaxf(v.z, v.w));
    __shared__ float red[8];
    __shared__ float bval;
#pragma unroll
    for (int o = 16; o; o >>= 1) mx = fmaxf(mx, __shfl_xor_sync(0xffffffffu, mx, o));
    if ((tid & 31) == 0) red[tid >> 5] = mx;
    __syncthreads();
    if (tid == 0) {
        float t = red[0];
#pragma unroll
        for (int i = 1; i < 8; i++) t = fmaxf(t, red[i]);
        bval = t;
    }
    __syncthreads();
    mx = bval;
    v.x = __expf(v.x - mx); v.y = __expf(v.y - mx);
    v.z = __expf(v.z - mx); v.w = __expf(v.w - mx);
    float sum = v.x + v.y + v.z + v.w;
    __syncthreads();
#pragma unroll
    for (int o = 16; o; o >>= 1) sum += __shfl_xor_sync(0xffffffffu, sum, o);
    if ((tid & 31) == 0) red[tid >> 5] = sum;
    __syncthreads();
    if (tid == 0) {
        float t = 0.f;
#pragma unroll
        for (int i = 0; i < 8; i++) t += red[i];
        bval = 1.f / t;
    }
    __syncthreads();
    float inv = bval;
    v.x *= inv; v.y *= inv; v.z *= inv; v.w *= inv;
    *reinterpret_cast<float4*>(row + 4 * tid) = v;
}

// ---------------- host ----------------
extern "C" void kernel_launch(void* const* d_in, const int* in_sizes, int n_in,
                              void* d_out, int out_size)
{
    (void)in_sizes; (void)n_in; (void)out_size;
    const float* x      = (const float*)d_in[0];
    const float* fc     = (const float*)d_in[1];
    /* mask d_in[2] handled analytically (start_pos == 0, causal) */
    const float* wq_a   = (const float*)d_in[3];
    const float* qnw    = (const float*)d_in[4];
    const float* wq_b   = (const float*)d_in[5];
    const float* wkv_a  = (const float*)d_in[6];
    const float* kvnw   = (const float*)d_in[7];
    const float* wkv_b  = (const float*)d_in[8];
    const float* wo     = (const float*)d_in[9];
    float* out = (float*)d_out;

    float *qlora, *kv, *kvcat, *q, *Kcat, *Vt, *scores, *proj;
    cudaGetSymbolAddress((void**)&qlora,  g_qlora);
    cudaGetSymbolAddress((void**)&kv,     g_kv);
    cudaGetSymbolAddress((void**)&kvcat,  g_kvcat);
    cudaGetSymbolAddress((void**)&q,      g_q);
    cudaGetSymbolAddress((void**)&Kcat,   g_Kcat);
    cudaGetSymbolAddress((void**)&Vt,     g_Vt);
    cudaGetSymbolAddress((void**)&scores, g_scores);
    cudaGetSymbolAddress((void**)&proj,   g_proj);

    // 1. qlora = x @ wq_a                [2048,1536]
    gemm_k<false, 0, false><<<dim3(12, 16, 1), 256>>>(
        x, wq_a, qlora, BS, QL, DIM, DIM, QL, QL, 0, 0, 0, 0, 0, 0, 1);
    // 2. kv = x @ wkv_a                  [2048,576]
    gemm_k<false, 0, false><<<dim3(5, 16, 1), 256>>>(
        x, wkv_a, kv, BS, CAT, DIM, DIM, CAT, CAT, 0, 0, 0, 0, 0, 0, 1);
    // 3. rmsnorm(qlora) in place
    rmsnorm_k<<<BS, 256>>>(qlora, qnw, QL);
    // 4. kvpost -> kvcat; k_pe broadcast into Kcat[...,128:192]
    kvpost_k<<<BS, 256>>>(kv, kvnw, fc, kvcat, Kcat);
    // 5. q = qlora @ wq_b                [2048,6144]
    gemm_k<false, 0, false><<<dim3(48, 16, 1), 256>>>(
        qlora, wq_b, q, BS, QD, QL, QL, QD, QD, 0, 0, 0, 0, 0, 0, 1);
    // 6. rope(q_pe) in place on q
    ropeq_k<<<BS, 256>>>(q, fc);
    // 7. K_head: Kcat[b][h][t][0:128] = kv_n @ wkvb1^T   (per b,h)
    //    A = kvcat (b)  [1024 t][512], lda=576 ; B = wkv_b[h][0:128] TB [128][512]
    gemm_k<true, 0, false><<<dim3(1, 8, 64), 256>>>(
        kvcat, wkv_b, Kcat, SS, NOPE, KVL,
        CAT, KVL, QKH,
        (LL)SS * CAT, 0,
        0, (LL)(NOPE + VD) * KVL,
        (LL)HH * SS * QKH, (LL)SS * QKH, HH);
    // 8. Vt: Vt[b][h][d][t] = wkvb2 @ kv_n^T             (per b,h)
    //    A = wkv_b[h][128:256] [128 d][512], B = kvcat (b) TB [1024 t][512]
    gemm_k<true, 0, false><<<dim3(8, 1, 64), 256>>>(
        wkv_b + (LL)NOPE * KVL, kvcat, Vt, VD, SS, KVL,
        KVL, CAT, SS,
        0, (LL)(NOPE + VD) * KVL,
        (LL)SS * CAT, 0,
        (LL)HH * VD * SS, (LL)VD * SS, HH);
    // 9. scores = q_head @ Kcat^T  (*SCALE + causal)     (per b,h), K=192
    gemm_k<true, 1, false><<<dim3(8, 8, 64), 256>>>(
        q, Kcat, scores, SS, SS, QKH,
        QD, QKH, SS,
        (LL)SS * QD, QKH,
        (LL)HH * SS * QKH, (LL)SS * QKH,
        (LL)HH * SS * SS, (LL)SS * SS, HH);
    // 10. softmax in place
    softmax_k<<<64 * SS, 256>>>(scores);
    // 11. PV: proj[bs][h*128+d] = P @ Vt^T (causal K bound)  (per b,h)
    gemm_k<true, 0, true><<<dim3(1, 8, 64), 256>>>(
        scores, Vt, proj, SS, VD, SS,
        SS, SS, DIM,
        (LL)HH * SS * SS, (LL)SS * SS,
        (LL)HH * VD * SS, (LL)VD * SS,
        (LL)SS * DIM, VD, HH);
    // 12. out = proj @ wo                [2048,4096]
    gemm_k<false, 0, false><<<dim3(32, 16, 1), 256>>>(
        proj, wo, out, BS, DIM, DIM, DIM, DIM, DIM, 0, 0, 0, 0, 0, 0, 1);
}

// round 9
// speedup vs baseline: 3.4458x; 1.1723x over previous
#include <cuda_runtime.h>
#include <cuda_bf16.h>
#include <cuda_fp16.h>
#include <cstdint>

typedef long long LL;

// ---------------- problem constants ----------------
#define BB   2
#define SS   1024
#define BS   2048          // B*S
#define DIM  4096
#define HH   32
#define QL   1536
#define KVL  512
#define NOPE 128
#define ROPE 64
#define VD   128
#define QKH  192           // NOPE+ROPE
#define CAT  576           // KVL+ROPE
#define QD   6144          // H*QKH

#define NEGV   (-1e9f)
#define SCALEV 0.07216878364870322f   // 192^-0.5
#define EPSV   1e-6f

// ---------------- scratch (device globals) ----------
__device__ float g_qlora[(LL)BS * QL];
__device__ float g_kv   [(LL)BS * CAT];
__device__ float g_kvcat[(LL)BS * CAT];          // [norm(c_kv) | rope(k_pe)]
__device__ float g_q    [(LL)BS * QD];           // rope applied in place on pe part
__device__ float g_Kcat [64LL * SS * QKH];       // (b,h,t,192) = [K_head | k_pe]
__device__ float g_Vt   [64LL * VD * SS];        // (b,h,d,t)   = V_head^T
__device__ float g_scores[64LL * SS * SS];       // (b,h,s,t)
__device__ float g_proj [(LL)BS * DIM];          // (bs, h*VD+d)

// ---------------- split-FP16 tensor-core tiled GEMM ----------------
// C[m,n] = sum_k A[m,k] * B(k,n) ; TB: B stored [N,K] row-major (A @ B^T)
// EPI==1: scores epilogue (v*SCALE + causal NEG) with fully-masked tile skip
// CK: causal K-bound (k limited to m0+128)
// NP: split passes. 3: ah*bh + ah*bl + al*bh (~2^-24 dropped).
//                   2: ah*bh + ah*bl        (A fp16-rounded; ~1.4e-4 rms)
// CTA tile 128x128, BK=16, 8 warps (2m x 4n), warp tile 64x32.
static const int BM = 128, BN = 128, BK = 16;
#define PK 12      // u32 pitch for [row][k2] tiles

__device__ __forceinline__ void split2(float x, float y, uint32_t& hi, uint32_t& lo) {
    __half hx = __float2half_rn(x), hy = __float2half_rn(y);
    float rx = x - __half2float(hx);
    float ry = y - __half2float(hy);
    __half2 h = __halves2half2(hx, hy);
    __half2 l = __floats2half2_rn(rx, ry);
    hi = *reinterpret_cast<uint32_t*>(&h);
    lo = *reinterpret_cast<uint32_t*>(&l);
}
__device__ __forceinline__ uint32_t hi2(float x, float y) {
    __half2 h = __floats2half2_rn(x, y);
    return *reinterpret_cast<uint32_t*>(&h);
}
__device__ __forceinline__ void mma16(float c[4], const uint32_t a[4], const uint32_t b[2]) {
    asm volatile(
        "mma.sync.aligned.m16n8k16.row.col.f32.f16.f16.f32 "
        "{%0,%1,%2,%3},{%4,%5,%6,%7},{%8,%9},{%0,%1,%2,%3};\n"
        : "+f"(c[0]), "+f"(c[1]), "+f"(c[2]), "+f"(c[3])
        : "r"(a[0]), "r"(a[1]), "r"(a[2]), "r"(a[3]), "r"(b[0]), "r"(b[1]));
}

template<bool TB, int EPI, bool CK, int NP>
__global__ __launch_bounds__(256, 2)
void gemm_k(const float* __restrict__ A, const float* __restrict__ Bp,
            float* __restrict__ C,
            int M, int N, int K,
            int lda, int ldb, int ldc,
            LL bA1, LL bA2, LL bB1, LL bB2, LL bC1, LL bC2, int nz2)
{
    const int z  = blockIdx.z;
    const int z1 = z / nz2;
    const int z2 = z - z1 * nz2;
    A  += z1 * bA1 + z2 * bA2;
    Bp += z1 * bB1 + z2 * bB2;
    C  += z1 * bC1 + z2 * bC2;

    const int m0  = blockIdx.y * BM;
    const int n0  = blockIdx.x * BN;
    const int tid = threadIdx.x;

    if (EPI == 1 && n0 >= m0 + BM) {
        for (int e = tid; e < BM * BN; e += 256) {
            int r = e >> 7, c = e & 127;
            if (n0 + c < N) C[(LL)(m0 + r) * ldc + n0 + c] = NEGV;
        }
        return;
    }

    __shared__ uint32_t Ah[BM * PK];
    __shared__ uint32_t Al[(NP == 3) ? BM * PK : 1];
    __shared__ uint32_t Bh[BN * PK], Bl[BN * PK];

    const int lane = tid & 31, warp = tid >> 5;
    const int wm = warp >> 2, wn = warp & 3;
    const int gp = lane >> 2, tg = lane & 3;

    float acc[4][4][4];
#pragma unroll
    for (int i = 0; i < 4; i++)
#pragma unroll
        for (int j = 0; j < 4; j++)
#pragma unroll
            for (int r = 0; r < 4; r++) acc[i][j][r] = 0.f;

    int Keff = K;
    if (CK) { int km = m0 + BM; Keff = (km < K) ? km : K; }

    const int am = tid >> 2;          // 0..63 rows (A / TB-B loads)
    const int ak = (tid & 3) << 2;    // k offset 0,4,8,12
    const int k2a = (tid & 3) << 1;   // k2 offset 0,2,4,6
    const int bnn  = tid & 127;
    const int bkh  = (tid >> 7) << 2;

    for (int k0 = 0; k0 < Keff; k0 += BK) {
        // ---- A tile -> [m][k2] (hi, + lo if NP==3)
#pragma unroll
        for (int p = 0; p < 2; p++) {
            int m = am + (p << 6);
            float4 v = *reinterpret_cast<const float4*>(
                A + (LL)(m0 + m) * lda + k0 + ak);
            if (NP == 3) {
                uint32_t h0, l0, h1, l1;
                split2(v.x, v.y, h0, l0);
                split2(v.z, v.w, h1, l1);
                Ah[m * PK + k2a]     = h0;  Ah[m * PK + k2a + 1] = h1;
                Al[m * PK + k2a]     = l0;  Al[m * PK + k2a + 1] = l1;
            } else {
                Ah[m * PK + k2a]     = hi2(v.x, v.y);
                Ah[m * PK + k2a + 1] = hi2(v.z, v.w);
            }
        }
        // ---- B tile -> [n][k2] (hi/lo)
        if (!TB) {   // gmem [k][n]: transpose in flight
#pragma unroll
            for (int q = 0; q < 4; q++) {
                int kk = bkh + q;
                float f0 = 0.f, f1 = 0.f;
                if (n0 + bnn < N) {
                    f0 = Bp[(LL)(k0 + 2 * kk)     * ldb + n0 + bnn];
                    f1 = Bp[(LL)(k0 + 2 * kk + 1) * ldb + n0 + bnn];
                }
                uint32_t h, l;
                split2(f0, f1, h, l);
                Bh[bnn * PK + kk] = h;
                Bl[bnn * PK + kk] = l;
            }
        } else {     // gmem [n][k]
#pragma unroll
            for (int p = 0; p < 2; p++) {
                int n = am + (p << 6);
                float4 v = make_float4(0.f, 0.f, 0.f, 0.f);
                if (n0 + n < N)
                    v = *reinterpret_cast<const float4*>(
                        Bp + (LL)(n0 + n) * ldb + k0 + ak);
                uint32_t h0, l0, h1, l1;
                split2(v.x, v.y, h0, l0);
                split2(v.z, v.w, h1, l1);
                Bh[n * PK + k2a]     = h0;  Bh[n * PK + k2a + 1] = h1;
                Bl[n * PK + k2a]     = l0;  Bl[n * PK + k2a + 1] = l1;
            }
        }
        __syncthreads();

        uint32_t bhf[4][2], blf[4][2];
#pragma unroll
        for (int nf = 0; nf < 4; nf++) {
            int nb = (wn << 5) + (nf << 3) + gp;
            bhf[nf][0] = Bh[nb * PK + tg];
            bhf[nf][1] = Bh[nb * PK + tg + 4];
            blf[nf][0] = Bl[nb * PK + tg];
            blf[nf][1] = Bl[nb * PK + tg + 4];
        }
#pragma unroll
        for (int mf = 0; mf < 4; mf++) {
            int mb = (wm << 6) + (mf << 4) + gp;
            int j0 = mb * PK + tg;
            int j1 = (mb + 8) * PK + tg;
            uint32_t ahf[4] = { Ah[j0], Ah[j1], Ah[j0 + 4], Ah[j1 + 4] };
#pragma unroll
            for (int nf = 0; nf < 4; nf++) {
                mma16(acc[mf][nf], ahf, bhf[nf]);
                mma16(acc[mf][nf], ahf, blf[nf]);
            }
            if (NP == 3) {
                uint32_t alf[4] = { Al[j0], Al[j1], Al[j0 + 4], Al[j1 + 4] };
#pragma unroll
                for (int nf = 0; nf < 4; nf++)
                    mma16(acc[mf][nf], alf, bhf[nf]);
            }
        }
        __syncthreads();
    }

    // ---- store
#pragma unroll
    for (int mf = 0; mf < 4; mf++) {
#pragma unroll
        for (int nf = 0; nf < 4; nf++) {
            int n = n0 + (wn << 5) + (nf << 3) + 2 * tg;
#pragma unroll
            for (int h = 0; h < 2; h++) {
                int m = m0 + (wm << 6) + (mf << 4) + gp + h * 8;
                float2 v = make_float2(acc[mf][nf][2 * h], acc[mf][nf][2 * h + 1]);
                if (EPI == 1) {
                    v.x = v.x * SCALEV + ((n + 0 > m) ? NEGV : 0.f);
                    v.y = v.y * SCALEV + ((n + 1 > m) ? NEGV : 0.f);
                }
                LL ro = (LL)m * ldc;
                if (n + 1 < N) {
                    *reinterpret_cast<float2*>(C + ro + n) = v;
                } else {
                    if (n < N) C[ro + n] = v.x;
                    if (n + 1 < N) C[ro + n + 1] = v.y;
                }
            }
        }
    }
}

// ---------------- rmsnorm (in place) ----------------
__global__ void rmsnorm_k(float* __restrict__ x, const float* __restrict__ w, int len)
{
    float* row = x + (LL)blockIdx.x * len;
    const int tid = threadIdx.x;
    float ss = 0.f;
    for (int i = tid; i < len; i += 256) { float v = row[i]; ss += v * v; }
    __shared__ float red[8];
    __shared__ float sc_s;
#pragma unroll
    for (int o = 16; o; o >>= 1) ss += __shfl_xor_sync(0xffffffffu, ss, o);
    if ((tid & 31) == 0) red[tid >> 5] = ss;
    __syncthreads();
    if (tid == 0) {
        float t = 0.f;
#pragma unroll
        for (int i = 0; i < 8; i++) t += red[i];
        sc_s = rsqrtf(t / (float)len + EPSV);
    }
    __syncthreads();
    float sc = sc_s;
    for (int i = tid; i < len; i += 256) row[i] = row[i] * sc * w[i];
}

// ---- kvpost: rmsnorm(c_kv)*w -> kvcat[0:512]; rope(k_pe) -> kvcat[512:576]
//      AND broadcast roped k_pe into Kcat[b][h][t][128:192] for all 32 heads.
__global__ void kvpost_k(const float* __restrict__ kv, const float* __restrict__ w,
                         const float* __restrict__ fc, float* __restrict__ o,
                         float* __restrict__ Kcat)
{
    const int bs = blockIdx.x;
    const float* row = kv + (LL)bs * CAT;
    float* out = o + (LL)bs * CAT;
    const int tid = threadIdx.x;
    float2 v = *reinterpret_cast<const float2*>(row + 2 * tid);
    float ss = v.x * v.x + v.y * v.y;
    __shared__ float red[8];
    __shared__ float sc_s;
#pragma unroll
    for (int oo = 16; oo; oo >>= 1) ss += __shfl_xor_sync(0xffffffffu, ss, oo);
    if ((tid & 31) == 0) red[tid >> 5] = ss;
    __syncthreads();
    if (tid == 0) {
        float t = 0.f;
#pragma unroll
        for (int i = 0; i < 8; i++) t += red[i];
        sc_s = rsqrtf(t / (float)KVL + EPSV);
    }
    __syncthreads();
    float sc = sc_s;
    *reinterpret_cast<float2*>(out + 2 * tid) =
        make_float2(v.x * sc * w[2 * tid], v.y * sc * w[2 * tid + 1]);
    if (tid < 32) {
        int t = bs & (SS - 1);
        int b = bs >> 10;
        float e  = row[KVL + 2 * tid];
        float od = row[KVL + 2 * tid + 1];
        float c  = fc[t * ROPE + 2 * tid];
        float sn = fc[t * ROPE + 2 * tid + 1];
        float re = e * c - od * sn;
        float ro = e * sn + od * c;
        out[KVL + 2 * tid]     = re;
        out[KVL + 2 * tid + 1] = ro;
        float2 pr = make_float2(re, ro);
#pragma unroll
        for (int h = 0; h < HH; h++) {
            LL base = (((LL)(b * HH + h)) * SS + t) * QKH + NOPE + 2 * tid;
            *reinterpret_cast<float2*>(Kcat + base) = pr;
        }
    }
}

// ---- rope(q_pe) IN PLACE on q[..., h*192+128 : h*192+192] ----
__global__ void ropeq_k(float* __restrict__ q, const float* __restrict__ fc)
{
    const int bs = blockIdx.x;
    const int s = bs & (SS - 1);
    for (int t = threadIdx.x; t < HH * 32; t += 256) {
        int h = t >> 5, i = t & 31;
        float* p = q + (LL)bs * QD + h * QKH + NOPE + 2 * i;
        float e = p[0], o = p[1];
        float c  = fc[s * ROPE + 2 * i];
        float sn = fc[s * ROPE + 2 * i + 1];
        p[0] = e * c - o * sn;
        p[1] = e * sn + o * c;
    }
}

// ---- softmax over rows of 1024 (in place, fp32) ----
__global__ void softmax_k(float* __restrict__ S)
{
    float* row = S + (LL)blockIdx.x * 1024;
    const int tid = threadIdx.x;
    float4 v = *reinterpret_cast<const float4*>(row + 4 * tid);
    float mx = fmaxf(fmaxf(v.x, v.y), fmaxf(v.z, v.w));
    __shared__ float red[8];
    __shared__ float bval;
#pragma unroll
    for (int o = 16; o; o >>= 1) mx = fmaxf(mx, __shfl_xor_sync(0xffffffffu, mx, o));
    if ((tid & 31) == 0) red[tid >> 5] = mx;
    __syncthreads();
    if (tid == 0) {
        float t = red[0];
#pragma unroll
        for (int i = 1; i < 8; i++) t = fmaxf(t, red[i]);
        bval = t;
    }
    __syncthreads();
    mx = bval;
    v.x = __expf(v.x - mx); v.y = __expf(v.y - mx);
    v.z = __expf(v.z - mx); v.w = __expf(v.w - mx);
    float sum = v.x + v.y + v.z + v.w;
    __syncthreads();
#pragma unroll
    for (int o = 16; o; o >>= 1) sum += __shfl_xor_sync(0xffffffffu, sum, o);
    if ((tid & 31) == 0) red[tid >> 5] = sum;
    __syncthreads();
    if (tid == 0) {
        float t = 0.f;
#pragma unroll
        for (int i = 0; i < 8; i++) t += red[i];
        bval = 1.f / t;
    }
    __syncthreads();
    float inv = bval;
    v.x *= inv; v.y *= inv; v.z *= inv; v.w *= inv;
    *reinterpret_cast<float4*>(row + 4 * tid) = v;
}

// ---------------- host ----------------
extern "C" void kernel_launch(void* const* d_in, const int* in_sizes, int n_in,
                              void* d_out, int out_size)
{
    (void)in_sizes; (void)n_in; (void)out_size;
    const float* x      = (const float*)d_in[0];
    const float* fc     = (const float*)d_in[1];
    /* mask d_in[2] handled analytically (start_pos == 0, causal) */
    const float* wq_a   = (const float*)d_in[3];
    const float* qnw    = (const float*)d_in[4];
    const float* wq_b   = (const float*)d_in[5];
    const float* wkv_a  = (const float*)d_in[6];
    const float* kvnw   = (const float*)d_in[7];
    const float* wkv_b  = (const float*)d_in[8];
    const float* wo     = (const float*)d_in[9];
    float* out = (float*)d_out;

    float *qlora, *kv, *kvcat, *q, *Kcat, *Vt, *scores, *proj;
    cudaGetSymbolAddress((void**)&qlora,  g_qlora);
    cudaGetSymbolAddress((void**)&kv,     g_kv);
    cudaGetSymbolAddress((void**)&kvcat,  g_kvcat);
    cudaGetSymbolAddress((void**)&q,      g_q);
    cudaGetSymbolAddress((void**)&Kcat,   g_Kcat);
    cudaGetSymbolAddress((void**)&Vt,     g_Vt);
    cudaGetSymbolAddress((void**)&scores, g_scores);
    cudaGetSymbolAddress((void**)&proj,   g_proj);

    // 1. qlora = x @ wq_a                [2048,1536]   (2-pass)
    gemm_k<false, 0, false, 2><<<dim3(12, 16, 1), 256>>>(
        x, wq_a, qlora, BS, QL, DIM, DIM, QL, QL, 0, 0, 0, 0, 0, 0, 1);
    // 2. kv = x @ wkv_a                  [2048,576]    (3-pass, kv path)
    gemm_k<false, 0, false, 3><<<dim3(5, 16, 1), 256>>>(
        x, wkv_a, kv, BS, CAT, DIM, DIM, CAT, CAT, 0, 0, 0, 0, 0, 0, 1);
    // 3. rmsnorm(qlora) in place
    rmsnorm_k<<<BS, 256>>>(qlora, qnw, QL);
    // 4. kvpost -> kvcat; k_pe broadcast into Kcat[...,128:192]
    kvpost_k<<<BS, 256>>>(kv, kvnw, fc, kvcat, Kcat);
    // 5. q = qlora @ wq_b                [2048,6144]   (2-pass)
    gemm_k<false, 0, false, 2><<<dim3(48, 16, 1), 256>>>(
        qlora, wq_b, q, BS, QD, QL, QL, QD, QD, 0, 0, 0, 0, 0, 0, 1);
    // 6. rope(q_pe) in place on q
    ropeq_k<<<BS, 256>>>(q, fc);
    // 7. K_head: Kcat[b][h][t][0:128] = kv_n @ wkvb1^T   (per b,h) (3-pass)
    gemm_k<true, 0, false, 3><<<dim3(1, 8, 64), 256>>>(
        kvcat, wkv_b, Kcat, SS, NOPE, KVL,
        CAT, KVL, QKH,
        (LL)SS * CAT, 0,
        0, (LL)(NOPE + VD) * KVL,
        (LL)HH * SS * QKH, (LL)SS * QKH, HH);
    // 8. Vt: Vt[b][h][d][t] = wkvb2 @ kv_n^T             (per b,h) (3-pass)
    gemm_k<true, 0, false, 3><<<dim3(8, 1, 64), 256>>>(
        wkv_b + (LL)NOPE * KVL, kvcat, Vt, VD, SS, KVL,
        KVL, CAT, SS,
        0, (LL)(NOPE + VD) * KVL,
        (LL)SS * CAT, 0,
        (LL)HH * VD * SS, (LL)VD * SS, HH);
    // 9. scores = q_head @ Kcat^T  (*SCALE + causal)     (per b,h) (3-pass)
    gemm_k<true, 1, false, 3><<<dim3(8, 8, 64), 256>>>(
        q, Kcat, scores, SS, SS, QKH,
        QD, QKH, SS,
        (LL)SS * QD, QKH,
        (LL)HH * SS * QKH, (LL)SS * QKH,
        (LL)HH * SS * SS, (LL)SS * SS, HH);
    // 10. softmax in place
    softmax_k<<<64 * SS, 256>>>(scores);
    // 11. PV: proj = P @ Vt^T (causal K bound)  (per b,h) (2-pass, A=P)
    gemm_k<true, 0, true, 2><<<dim3(1, 8, 64), 256>>>(
        scores, Vt, proj, SS, VD, SS,
        SS, SS, DIM,
        (LL)HH * SS * SS, (LL)SS * SS,
        (LL)HH * VD * SS, (LL)VD * SS,
        (LL)SS * DIM, VD, HH);
    // 12. out = proj @ wo                [2048,4096]   (2-pass)
    gemm_k<false, 0, false, 2><<<dim3(32, 16, 1), 256>>>(
        proj, wo, out, BS, DIM, DIM, DIM, DIM, DIM, 0, 0, 0, 0, 0, 0, 1);
}